// round 9
// baseline (speedup 1.0000x reference)
#include <cuda_runtime.h>
#include <cstdint>

#define NROWS   8192
#define KDIM    512
#define NPCAS   128
#define NSTACKS 64
#define OUTDIM  8192

#define COEFF_F   3.7712361663282537f
#define TWO_PI_F  6.283185307179586f

__device__ float g_xproj[NROWS * NPCAS];

// ---------------------------------------------------------------------------
// Kernel 1: unchanged (bit-matches reference; sequential-k FMA).
// ---------------------------------------------------------------------------
__global__ __launch_bounds__(256, 2)
void gemm_kernel(const float* __restrict__ A, const float* __restrict__ B,
                 float* __restrict__ C)
{
    __shared__ float As[64 * 64];
    __shared__ float Bs[64 * 128];

    const int tid  = threadIdx.x;
    const int r0   = blockIdx.x * 64;
    const int warp = tid >> 5;
    const int lane = tid & 31;
    const int rbase = warp * 8;
    const int cb    = lane * 4;

    float acc[8][4];
#pragma unroll
    for (int i = 0; i < 8; i++)
#pragma unroll
        for (int j = 0; j < 4; j++) acc[i][j] = 0.0f;

    for (int kc = 0; kc < KDIM; kc += 64) {
        __syncthreads();
#pragma unroll
        for (int i = 0; i < 4; i++) {
            int idx = tid + i * 256;
            int row = idx >> 4;
            int k4  = idx & 15;
            ((float4*)As)[row * 16 + k4] =
                *(const float4*)(A + (size_t)(r0 + row) * KDIM + kc + k4 * 4);
        }
#pragma unroll
        for (int i = 0; i < 8; i++) {
            int idx = tid + i * 256;
            int kk  = idx >> 5;
            int c4  = idx & 31;
            ((float4*)Bs)[kk * 32 + c4] =
                *(const float4*)(B + (size_t)(kc + kk) * NPCAS + c4 * 4);
        }
        __syncthreads();

#pragma unroll 8
        for (int kk = 0; kk < 64; kk++) {
            float4 b4 = ((const float4*)Bs)[kk * 32 + lane];
#pragma unroll
            for (int i = 0; i < 8; i++) {
                float a = As[(rbase + i) * 64 + kk];
                acc[i][0] = fmaf(a, b4.x, acc[i][0]);
                acc[i][1] = fmaf(a, b4.y, acc[i][1]);
                acc[i][2] = fmaf(a, b4.z, acc[i][2]);
                acc[i][3] = fmaf(a, b4.w, acc[i][3]);
            }
        }
    }

#pragma unroll
    for (int i = 0; i < 8; i++) {
        float4 v = make_float4(acc[i][0], acc[i][1], acc[i][2], acc[i][3]);
        *(float4*)(C + (size_t)(r0 + rbase + i) * NPCAS + cb) = v;
    }
}

// ---------------------------------------------------------------------------
// Packed f32x2 helpers. R7 lesson: never emit packed mul.rn followed by packed
// add.rn where two roundings are required — ptxas fuses them into fma.rn.f32x2.
// ---------------------------------------------------------------------------
typedef unsigned long long u64t;

__device__ __forceinline__ u64t pack2(float lo, float hi) {
    u64t r; asm("mov.b64 %0, {%1, %2};" : "=l"(r) : "f"(lo), "f"(hi)); return r;
}
__device__ __forceinline__ void unpack2(u64t v, float& lo, float& hi) {
    asm("mov.b64 {%0, %1}, %2;" : "=f"(lo), "=f"(hi) : "l"(v));
}
__device__ __forceinline__ u64t fma2(u64t a, u64t b, u64t c) {
    u64t r; asm("fma.rn.f32x2 %0, %1, %2, %3;" : "=l"(r) : "l"(a), "l"(b), "l"(c)); return r;
}
__device__ __forceinline__ u64t mul2(u64t a, u64t b) {
    u64t r; asm("mul.rn.f32x2 %0, %1, %2;" : "=l"(r) : "l"(a), "l"(b)); return r;
}

// Packed cos, per-half bit-identical to the scalar fast_cos (R4-verified).
__device__ __forceinline__ void fast_cos2(u64t X, float& o0, float& o1)
{
    const u64t INV2   = pack2(0.6366197723675814f, 0.6366197723675814f);
    const u64t MAG2   = pack2(12582912.0f, 12582912.0f);
    const u64t NMAG2  = pack2(-12582912.0f, -12582912.0f);
    const u64t NPIH2  = pack2(-1.5707963705062866f, -1.5707963705062866f);
    const u64t PIL2   = pack2(4.3711388286737929e-8f, 4.3711388286737929e-8f);
    const u64t CC3    = pack2(2.443315711809948e-5f, 2.443315711809948e-5f);
    const u64t CC2    = pack2(-1.388731625493765e-3f, -1.388731625493765e-3f);
    const u64t CC1    = pack2(4.166664568298827e-2f, 4.166664568298827e-2f);
    const u64t CHALF  = pack2(-0.5f, -0.5f);
    const u64t CONE   = pack2(1.0f, 1.0f);
    const u64t SS3    = pack2(-1.9515295891e-4f, -1.9515295891e-4f);
    const u64t SS2    = pack2(8.3321608736e-3f, 8.3321608736e-3f);
    const u64t SS1    = pack2(-1.6666654611e-1f, -1.6666654611e-1f);

    u64t T = fma2(X, INV2, MAG2);
    float tlo, thi; unpack2(T, tlo, thi);
    int q0 = __float_as_int(tlo);
    int q1 = __float_as_int(thi);
    u64t Q = fma2(T, CONE, NMAG2);   // exact (Sterbenz), single rounding
    u64t R = fma2(Q, NPIH2, X);
    R = fma2(Q, PIL2, R);
    u64t S = mul2(R, R);             // feeds fma2 only — fusion-safe

    u64t PC = fma2(S, CC3, CC2);
    PC = fma2(S, PC, CC1);
    PC = fma2(S, PC, CHALF);
    PC = fma2(S, PC, CONE);

    u64t PS = fma2(S, SS3, SS2);
    PS = fma2(S, PS, SS1);
    u64t SR = mul2(S, R);            // feeds fma2 as multiplicand — safe
    PS = fma2(PS, SR, R);

    float pc0, pc1, ps0, ps1;
    unpack2(PC, pc0, pc1);
    unpack2(PS, ps0, ps1);

    float v0 = (q0 & 1) ? ps0 : pc0;
    float v1 = (q1 & 1) ? ps1 : pc1;
    o0 = __int_as_float(__float_as_int(v0) ^ (int)(((unsigned)(q0 + 1) & 2u) << 30));
    o1 = __int_as_float(__float_as_int(v1) ^ (int)(((unsigned)(q1 + 1) & 2u) << 30));
}

// ---------------------------------------------------------------------------
// 128-pt FWHT, 16 consecutive elements per lane (element = (lane&7)*16 + j),
// 8-lane octet per row. Stages h=1..8 in-register (+/- exactly as reference),
// h=16,32,64 cross-lane via fmaf(±1, f, p) (rounds identically to ±f + p).
// Same butterfly pairs, same ascending stage order => bit-identical.
// ---------------------------------------------------------------------------
__device__ __forceinline__ void fwht128_16(float f[16], const unsigned w[16],
                                           float sgA, float sgB, float sgC)
{
#pragma unroll
    for (int j = 0; j < 16; j++)
        f[j] = __int_as_float(__float_as_int(f[j]) ^ ((int)w[j] & 0x80000000));
    // h = 1
#pragma unroll
    for (int k = 0; k < 8; k++) {
        float a = f[2*k], b = f[2*k+1];
        f[2*k] = a + b; f[2*k+1] = a - b;
    }
    // h = 2
#pragma unroll
    for (int g = 0; g < 4; g++)
#pragma unroll
        for (int j = 0; j < 2; j++) {
            int i0 = g*4 + j;
            float a = f[i0], b = f[i0+2];
            f[i0] = a + b; f[i0+2] = a - b;
        }
    // h = 4
#pragma unroll
    for (int g = 0; g < 2; g++)
#pragma unroll
        for (int j = 0; j < 4; j++) {
            int i0 = g*8 + j;
            float a = f[i0], b = f[i0+4];
            f[i0] = a + b; f[i0+4] = a - b;
        }
    // h = 8
#pragma unroll
    for (int j = 0; j < 8; j++) {
        float a = f[j], b = f[j+8];
        f[j] = a + b; f[j+8] = a - b;
    }
    // h = 16, 32, 64 : cross-lane (octet bits 0,1,2)
#pragma unroll
    for (int j = 0; j < 16; j++) {
        float p = __shfl_xor_sync(0xffffffffu, f[j], 1);
        f[j] = fmaf(sgA, f[j], p);
    }
#pragma unroll
    for (int j = 0; j < 16; j++) {
        float p = __shfl_xor_sync(0xffffffffu, f[j], 2);
        f[j] = fmaf(sgB, f[j], p);
    }
#pragma unroll
    for (int j = 0; j < 16; j++) {
        float p = __shfl_xor_sync(0xffffffffu, f[j], 4);
        f[j] = fmaf(sgC, f[j], p);
    }
}

// ---------------------------------------------------------------------------
// Kernel 2: warp item = (row-quad, stack-quad). Warp holds 4 rows (lane>>3),
// each row spread over an 8-lane octet, 16 elems/lane.
// ---------------------------------------------------------------------------
#define K2_BLOCKS  444          // 148 * 3
#define K2_THREADS 256
#define K2_NW      (K2_BLOCKS * K2_THREADS / 32)
#define NITEMS     ((NROWS / 4) * 16)      // 32768

__global__ __launch_bounds__(K2_THREADS, 2)
void fwht_cos_kernel(const float* __restrict__ xp, const float* __restrict__ d,
                     const float* __restrict__ b, float* __restrict__ out)
{
    const int lane = threadIdx.x & 31;
    const int oct  = lane & 7;
    const int rg   = lane >> 3;
    const int gw   = (blockIdx.x * K2_THREADS + threadIdx.x) >> 5;
    const int e0   = oct * 16;

    const float sgA = (oct & 1) ? -1.0f : 1.0f;
    const float sgB = (oct & 2) ? -1.0f : 1.0f;
    const float sgC = (oct & 4) ? -1.0f : 1.0f;

    for (int item = gw; item < NITEMS; item += K2_NW) {
        const int rq = item >> 4;
        const int sq = item & 15;
        const int r  = rq * 4 + rg;

        float xv[16];
        {
            const float4* xr = (const float4*)(xp + (size_t)r * NPCAS + e0);
#pragma unroll
            for (int i = 0; i < 4; i++) {
                float4 v = xr[i];
                xv[4*i+0] = v.x; xv[4*i+1] = v.y; xv[4*i+2] = v.z; xv[4*i+3] = v.w;
            }
        }
        float* orow = out + (size_t)r * OUTDIM;

#pragma unroll
        for (int si = 0; si < 4; si++) {
            const int s    = sq * 4 + si;
            const int base = s * NPCAS + e0;

            unsigned w0[16], w1[16];
            {
                const uint4* dq0 = (const uint4*)(d + base);
                const uint4* dq1 = (const uint4*)(d + NSTACKS * NPCAS + base);
#pragma unroll
                for (int i = 0; i < 4; i++) {
                    uint4 q0 = dq0[i], q1 = dq1[i];
                    w0[4*i+0] = q0.x; w0[4*i+1] = q0.y; w0[4*i+2] = q0.z; w0[4*i+3] = q0.w;
                    w1[4*i+0] = q1.x; w1[4*i+1] = q1.y; w1[4*i+2] = q1.z; w1[4*i+3] = q1.w;
                }
            }
            float bb[16];
            {
                const float4* bq = (const float4*)(b + base);
#pragma unroll
                for (int i = 0; i < 4; i++) {
                    float4 v = bq[i];
                    bb[4*i+0] = __fmul_rn(v.x, TWO_PI_F);
                    bb[4*i+1] = __fmul_rn(v.y, TWO_PI_F);
                    bb[4*i+2] = __fmul_rn(v.z, TWO_PI_F);
                    bb[4*i+3] = __fmul_rn(v.w, TWO_PI_F);
                }
            }

            float f[16];
#pragma unroll
            for (int j = 0; j < 16; j++) f[j] = xv[j];

            fwht128_16(f, w0, sgA, sgB, sgC);
#pragma unroll
            for (int j = 0; j < 16; j++) f[j] = __fmul_rn(f[j], COEFF_F);
            fwht128_16(f, w1, sgA, sgB, sgC);

            // SEPARATE scalar mul then add (two roundings) — matches reference
            float a[16];
#pragma unroll
            for (int j = 0; j < 16; j++)
                a[j] = __fadd_rn(__fmul_rn(f[j], COEFF_F), bb[j]);

            float o[16];
#pragma unroll
            for (int j = 0; j < 8; j++)
                fast_cos2(pack2(a[2*j], a[2*j+1]), o[2*j], o[2*j+1]);

#pragma unroll
            for (int i = 0; i < 4; i++) {
                float4 v = make_float4(o[4*i+0], o[4*i+1], o[4*i+2], o[4*i+3]);
                *(float4*)(orow + base + 4*i) = v;
            }
        }
    }
}

// ---------------------------------------------------------------------------
extern "C" void kernel_launch(void* const* d_in, const int* in_sizes, int n_in,
                              void* d_out, int out_size)
{
    const float* x    = (const float*)d_in[0];
    const float* proj = (const float*)d_in[1];
    const float* d    = (const float*)d_in[2];
    const float* b    = (const float*)d_in[3];
    float* out        = (float*)d_out;

    float* xproj;
    cudaGetSymbolAddress((void**)&xproj, g_xproj);

    gemm_kernel<<<NROWS / 64, 256>>>(x, proj, xproj);
    fwht_cos_kernel<<<K2_BLOCKS, K2_THREADS>>>(xproj, d, b, out);
}

// round 10
// speedup vs baseline: 1.4094x; 1.4094x over previous
#include <cuda_runtime.h>
#include <cstdint>

#define NROWS   8192
#define KDIM    512
#define NPCAS   128
#define NSTACKS 64
#define OUTDIM  8192

#define COEFF_F   3.7712361663282537f
#define TWO_PI_F  6.283185307179586f

__device__ float g_xproj[NROWS * NPCAS];

// ---------------------------------------------------------------------------
// Kernel 1: unchanged (bit-matches reference; sequential-k FMA).
// ---------------------------------------------------------------------------
__global__ __launch_bounds__(256, 2)
void gemm_kernel(const float* __restrict__ A, const float* __restrict__ B,
                 float* __restrict__ C)
{
    __shared__ float As[64 * 64];
    __shared__ float Bs[64 * 128];

    const int tid  = threadIdx.x;
    const int r0   = blockIdx.x * 64;
    const int warp = tid >> 5;
    const int lane = tid & 31;
    const int rbase = warp * 8;
    const int cb    = lane * 4;

    float acc[8][4];
#pragma unroll
    for (int i = 0; i < 8; i++)
#pragma unroll
        for (int j = 0; j < 4; j++) acc[i][j] = 0.0f;

    for (int kc = 0; kc < KDIM; kc += 64) {
        __syncthreads();
#pragma unroll
        for (int i = 0; i < 4; i++) {
            int idx = tid + i * 256;
            int row = idx >> 4;
            int k4  = idx & 15;
            ((float4*)As)[row * 16 + k4] =
                *(const float4*)(A + (size_t)(r0 + row) * KDIM + kc + k4 * 4);
        }
#pragma unroll
        for (int i = 0; i < 8; i++) {
            int idx = tid + i * 256;
            int kk  = idx >> 5;
            int c4  = idx & 31;
            ((float4*)Bs)[kk * 32 + c4] =
                *(const float4*)(B + (size_t)(kc + kk) * NPCAS + c4 * 4);
        }
        __syncthreads();

#pragma unroll 8
        for (int kk = 0; kk < 64; kk++) {
            float4 b4 = ((const float4*)Bs)[kk * 32 + lane];
#pragma unroll
            for (int i = 0; i < 8; i++) {
                float a = As[(rbase + i) * 64 + kk];
                acc[i][0] = fmaf(a, b4.x, acc[i][0]);
                acc[i][1] = fmaf(a, b4.y, acc[i][1]);
                acc[i][2] = fmaf(a, b4.z, acc[i][2]);
                acc[i][3] = fmaf(a, b4.w, acc[i][3]);
            }
        }
    }

#pragma unroll
    for (int i = 0; i < 8; i++) {
        float4 v = make_float4(acc[i][0], acc[i][1], acc[i][2], acc[i][3]);
        *(float4*)(C + (size_t)(r0 + rbase + i) * NPCAS + cb) = v;
    }
}

// ---------------------------------------------------------------------------
// Packed f32x2 helpers. R7 lesson: never emit packed mul.rn feeding packed
// add.rn where two roundings are required — ptxas fuses them into fma.
// ---------------------------------------------------------------------------
typedef unsigned long long u64t;

__device__ __forceinline__ u64t pack2(float lo, float hi) {
    u64t r; asm("mov.b64 %0, {%1, %2};" : "=l"(r) : "f"(lo), "f"(hi)); return r;
}
__device__ __forceinline__ void unpack2(u64t v, float& lo, float& hi) {
    asm("mov.b64 {%0, %1}, %2;" : "=f"(lo), "=f"(hi) : "l"(v));
}
__device__ __forceinline__ u64t fma2(u64t a, u64t b, u64t c) {
    u64t r; asm("fma.rn.f32x2 %0, %1, %2, %3;" : "=l"(r) : "l"(a), "l"(b), "l"(c)); return r;
}
__device__ __forceinline__ u64t mul2(u64t a, u64t b) {
    u64t r; asm("mul.rn.f32x2 %0, %1, %2;" : "=l"(r) : "l"(a), "l"(b)); return r;
}

// Packed cos, per-half bit-identical to the scalar fast_cos (R4-verified).
__device__ __forceinline__ void fast_cos2(u64t X, float& o0, float& o1)
{
    const u64t INV2   = pack2(0.6366197723675814f, 0.6366197723675814f);
    const u64t MAG2   = pack2(12582912.0f, 12582912.0f);
    const u64t NMAG2  = pack2(-12582912.0f, -12582912.0f);
    const u64t NPIH2  = pack2(-1.5707963705062866f, -1.5707963705062866f);
    const u64t PIL2   = pack2(4.3711388286737929e-8f, 4.3711388286737929e-8f);
    const u64t CC3    = pack2(2.443315711809948e-5f, 2.443315711809948e-5f);
    const u64t CC2    = pack2(-1.388731625493765e-3f, -1.388731625493765e-3f);
    const u64t CC1    = pack2(4.166664568298827e-2f, 4.166664568298827e-2f);
    const u64t CHALF  = pack2(-0.5f, -0.5f);
    const u64t CONE   = pack2(1.0f, 1.0f);
    const u64t SS3    = pack2(-1.9515295891e-4f, -1.9515295891e-4f);
    const u64t SS2    = pack2(8.3321608736e-3f, 8.3321608736e-3f);
    const u64t SS1    = pack2(-1.6666654611e-1f, -1.6666654611e-1f);

    u64t T = fma2(X, INV2, MAG2);
    float tlo, thi; unpack2(T, tlo, thi);
    int q0 = __float_as_int(tlo);
    int q1 = __float_as_int(thi);
    u64t Q = fma2(T, CONE, NMAG2);   // exact (Sterbenz), single rounding
    u64t R = fma2(Q, NPIH2, X);
    R = fma2(Q, PIL2, R);
    u64t S = mul2(R, R);             // feeds fma2 only — fusion-safe

    u64t PC = fma2(S, CC3, CC2);
    PC = fma2(S, PC, CC1);
    PC = fma2(S, PC, CHALF);
    PC = fma2(S, PC, CONE);

    u64t PS = fma2(S, SS3, SS2);
    PS = fma2(S, PS, SS1);
    u64t SR = mul2(S, R);            // feeds fma2 as multiplicand — safe
    PS = fma2(PS, SR, R);

    float pc0, pc1, ps0, ps1;
    unpack2(PC, pc0, pc1);
    unpack2(PS, ps0, ps1);

    float v0 = (q0 & 1) ? ps0 : pc0;
    float v1 = (q1 & 1) ? ps1 : pc1;
    o0 = __int_as_float(__float_as_int(v0) ^ (int)(((unsigned)(q0 + 1) & 2u) << 30));
    o1 = __int_as_float(__float_as_int(v1) ^ (int)(((unsigned)(q1 + 1) & 2u) << 30));
}

__device__ __forceinline__ float xsn(float f, unsigned w)
{
    return __int_as_float(__float_as_int(f) ^ ((int)w & 0x80000000));
}

// ---------------------------------------------------------------------------
// 128-pt FWHT, 16 consecutive elems/lane (element = (lane&7)*16 + j), 8-lane
// octet per row. Stages h=1..8 in-register, h=16/32/64 cross-lane via
// fmaf(±1, f, p). Bit-identical to reference ordering (validated R9).
// ---------------------------------------------------------------------------
__device__ __forceinline__ void fwht128_16(float f[16], float sgA, float sgB, float sgC)
{
    // h = 1
#pragma unroll
    for (int k = 0; k < 8; k++) {
        float a = f[2*k], b = f[2*k+1];
        f[2*k] = a + b; f[2*k+1] = a - b;
    }
    // h = 2
#pragma unroll
    for (int g = 0; g < 4; g++)
#pragma unroll
        for (int j = 0; j < 2; j++) {
            int i0 = g*4 + j;
            float a = f[i0], b = f[i0+2];
            f[i0] = a + b; f[i0+2] = a - b;
        }
    // h = 4
#pragma unroll
    for (int g = 0; g < 2; g++)
#pragma unroll
        for (int j = 0; j < 4; j++) {
            int i0 = g*8 + j;
            float a = f[i0], b = f[i0+4];
            f[i0] = a + b; f[i0+4] = a - b;
        }
    // h = 8
#pragma unroll
    for (int j = 0; j < 8; j++) {
        float a = f[j], b = f[j+8];
        f[j] = a + b; f[j+8] = a - b;
    }
    // h = 16, 32, 64 : cross-lane
#pragma unroll
    for (int j = 0; j < 16; j++) {
        float p = __shfl_xor_sync(0xffffffffu, f[j], 1);
        f[j] = fmaf(sgA, f[j], p);
    }
#pragma unroll
    for (int j = 0; j < 16; j++) {
        float p = __shfl_xor_sync(0xffffffffu, f[j], 2);
        f[j] = fmaf(sgB, f[j], p);
    }
#pragma unroll
    for (int j = 0; j < 16; j++) {
        float p = __shfl_xor_sync(0xffffffffu, f[j], 4);
        f[j] = fmaf(sgC, f[j], p);
    }
}

// ---------------------------------------------------------------------------
// Kernel 2: item = (row-quad, stack). Warp holds 4 rows (lane>>3), one stack.
// Only f[16] persists; d-signs XORed in transiently, b loaded at the end,
// cos computed in place. 131072 items / 3552 warps.
// ---------------------------------------------------------------------------
#define K2_BLOCKS  444          // 148 * 3
#define K2_THREADS 256
#define K2_NW      (K2_BLOCKS * K2_THREADS / 32)
#define NITEMS     ((NROWS / 4) * NSTACKS)    // 131072

__global__ __launch_bounds__(K2_THREADS, 3)
void fwht_cos_kernel(const float* __restrict__ xp, const float* __restrict__ d,
                     const float* __restrict__ b, float* __restrict__ out)
{
    const int lane = threadIdx.x & 31;
    const int oct  = lane & 7;
    const int rg   = lane >> 3;
    const int gw   = (blockIdx.x * K2_THREADS + threadIdx.x) >> 5;
    const int e0   = oct * 16;

    const float sgA = (oct & 1) ? -1.0f : 1.0f;
    const float sgB = (oct & 2) ? -1.0f : 1.0f;
    const float sgC = (oct & 4) ? -1.0f : 1.0f;

    for (int item = gw; item < NITEMS; item += K2_NW) {
        const int s    = item & (NSTACKS - 1);
        const int rq   = item >> 6;
        const int r    = rq * 4 + rg;
        const int base = s * NPCAS + e0;

        float f[16];
        // load x row slice
        {
            const float4* xr = (const float4*)(xp + (size_t)r * NPCAS + e0);
#pragma unroll
            for (int i = 0; i < 4; i++) {
                float4 v = xr[i];
                f[4*i+0] = v.x; f[4*i+1] = v.y; f[4*i+2] = v.z; f[4*i+3] = v.w;
            }
        }
        // apply d0 signs (transient)
        {
            const uint4* dq = (const uint4*)(d + base);
#pragma unroll
            for (int i = 0; i < 4; i++) {
                uint4 q = dq[i];
                f[4*i+0] = xsn(f[4*i+0], q.x); f[4*i+1] = xsn(f[4*i+1], q.y);
                f[4*i+2] = xsn(f[4*i+2], q.z); f[4*i+3] = xsn(f[4*i+3], q.w);
            }
        }
        fwht128_16(f, sgA, sgB, sgC);
#pragma unroll
        for (int j = 0; j < 16; j++) f[j] = __fmul_rn(f[j], COEFF_F);

        // apply d1 signs (transient)
        {
            const uint4* dq = (const uint4*)(d + NSTACKS * NPCAS + base);
#pragma unroll
            for (int i = 0; i < 4; i++) {
                uint4 q = dq[i];
                f[4*i+0] = xsn(f[4*i+0], q.x); f[4*i+1] = xsn(f[4*i+1], q.y);
                f[4*i+2] = xsn(f[4*i+2], q.z); f[4*i+3] = xsn(f[4*i+3], q.w);
            }
        }
        fwht128_16(f, sgA, sgB, sgC);

        // SEPARATE scalar mul then add (two roundings) — matches reference
        {
            const float4* bq = (const float4*)(b + base);
#pragma unroll
            for (int i = 0; i < 4; i++) {
                float4 v = bq[i];
                f[4*i+0] = __fadd_rn(__fmul_rn(f[4*i+0], COEFF_F), __fmul_rn(v.x, TWO_PI_F));
                f[4*i+1] = __fadd_rn(__fmul_rn(f[4*i+1], COEFF_F), __fmul_rn(v.y, TWO_PI_F));
                f[4*i+2] = __fadd_rn(__fmul_rn(f[4*i+2], COEFF_F), __fmul_rn(v.z, TWO_PI_F));
                f[4*i+3] = __fadd_rn(__fmul_rn(f[4*i+3], COEFF_F), __fmul_rn(v.w, TWO_PI_F));
            }
        }
        // cos in place
#pragma unroll
        for (int j = 0; j < 8; j++)
            fast_cos2(pack2(f[2*j], f[2*j+1]), f[2*j], f[2*j+1]);

        // store
        float* orow = out + (size_t)r * OUTDIM + base;
#pragma unroll
        for (int i = 0; i < 4; i++)
            *(float4*)(orow + 4*i) = make_float4(f[4*i+0], f[4*i+1], f[4*i+2], f[4*i+3]);
    }
}

// ---------------------------------------------------------------------------
extern "C" void kernel_launch(void* const* d_in, const int* in_sizes, int n_in,
                              void* d_out, int out_size)
{
    const float* x    = (const float*)d_in[0];
    const float* proj = (const float*)d_in[1];
    const float* d    = (const float*)d_in[2];
    const float* b    = (const float*)d_in[3];
    float* out        = (float*)d_out;

    float* xproj;
    cudaGetSymbolAddress((void**)&xproj, g_xproj);

    gemm_kernel<<<NROWS / 64, 256>>>(x, proj, xproj);
    fwht_cos_kernel<<<K2_BLOCKS, K2_THREADS>>>(xproj, d, b, out);
}

// round 12
// speedup vs baseline: 1.9533x; 1.3859x over previous
#include <cuda_runtime.h>
#include <cstdint>

#define NROWS   8192
#define KDIM    512
#define NPCAS   128
#define NSTACKS 64
#define OUTDIM  8192

#define COEFF_F   3.7712361663282537f
#define TWO_PI_F  6.283185307179586f

__device__ float g_xproj[NROWS * NPCAS];

// ---------------------------------------------------------------------------
// Kernel 1: unchanged (bit-matches reference; sequential-k FMA; ~95% of the
// fma-pipe roofline already).
// ---------------------------------------------------------------------------
__global__ __launch_bounds__(256, 2)
void gemm_kernel(const float* __restrict__ A, const float* __restrict__ B,
                 float* __restrict__ C)
{
    __shared__ float As[64 * 64];
    __shared__ float Bs[64 * 128];

    const int tid  = threadIdx.x;
    const int r0   = blockIdx.x * 64;
    const int warp = tid >> 5;
    const int lane = tid & 31;
    const int rbase = warp * 8;
    const int cb    = lane * 4;

    float acc[8][4];
#pragma unroll
    for (int i = 0; i < 8; i++)
#pragma unroll
        for (int j = 0; j < 4; j++) acc[i][j] = 0.0f;

    for (int kc = 0; kc < KDIM; kc += 64) {
        __syncthreads();
#pragma unroll
        for (int i = 0; i < 4; i++) {
            int idx = tid + i * 256;
            int row = idx >> 4;
            int k4  = idx & 15;
            ((float4*)As)[row * 16 + k4] =
                *(const float4*)(A + (size_t)(r0 + row) * KDIM + kc + k4 * 4);
        }
#pragma unroll
        for (int i = 0; i < 8; i++) {
            int idx = tid + i * 256;
            int kk  = idx >> 5;
            int c4  = idx & 31;
            ((float4*)Bs)[kk * 32 + c4] =
                *(const float4*)(B + (size_t)(kc + kk) * NPCAS + c4 * 4);
        }
        __syncthreads();

#pragma unroll 8
        for (int kk = 0; kk < 64; kk++) {
            float4 b4 = ((const float4*)Bs)[kk * 32 + lane];
#pragma unroll
            for (int i = 0; i < 8; i++) {
                float a = As[(rbase + i) * 64 + kk];
                acc[i][0] = fmaf(a, b4.x, acc[i][0]);
                acc[i][1] = fmaf(a, b4.y, acc[i][1]);
                acc[i][2] = fmaf(a, b4.z, acc[i][2]);
                acc[i][3] = fmaf(a, b4.w, acc[i][3]);
            }
        }
    }

#pragma unroll
    for (int i = 0; i < 8; i++) {
        float4 v = make_float4(acc[i][0], acc[i][1], acc[i][2], acc[i][3]);
        *(float4*)(C + (size_t)(r0 + rbase + i) * NPCAS + cb) = v;
    }
}

// ---------------------------------------------------------------------------
// Packed f32x2 helpers. R7 lesson: never emit packed mul.rn feeding packed
// add.rn where two roundings are required — ptxas fuses them into fma.
// ---------------------------------------------------------------------------
typedef unsigned long long u64t;

__device__ __forceinline__ u64t pack2(float lo, float hi) {
    u64t r; asm("mov.b64 %0, {%1, %2};" : "=l"(r) : "f"(lo), "f"(hi)); return r;
}
__device__ __forceinline__ void unpack2(u64t v, float& lo, float& hi) {
    asm("mov.b64 {%0, %1}, %2;" : "=f"(lo), "=f"(hi) : "l"(v));
}
__device__ __forceinline__ u64t fma2(u64t a, u64t b, u64t c) {
    u64t r; asm("fma.rn.f32x2 %0, %1, %2, %3;" : "=l"(r) : "l"(a), "l"(b), "l"(c)); return r;
}
__device__ __forceinline__ u64t mul2(u64t a, u64t b) {
    u64t r; asm("mul.rn.f32x2 %0, %1, %2;" : "=l"(r) : "l"(a), "l"(b)); return r;
}

// Packed cos, per-half bit-identical to the scalar fast_cos (R4-verified).
__device__ __forceinline__ void fast_cos2(u64t X, float& o0, float& o1)
{
    const u64t INV2   = pack2(0.6366197723675814f, 0.6366197723675814f);
    const u64t MAG2   = pack2(12582912.0f, 12582912.0f);
    const u64t NMAG2  = pack2(-12582912.0f, -12582912.0f);
    const u64t NPIH2  = pack2(-1.5707963705062866f, -1.5707963705062866f);
    const u64t PIL2   = pack2(4.3711388286737929e-8f, 4.3711388286737929e-8f);
    const u64t CC3    = pack2(2.443315711809948e-5f, 2.443315711809948e-5f);
    const u64t CC2    = pack2(-1.388731625493765e-3f, -1.388731625493765e-3f);
    const u64t CC1    = pack2(4.166664568298827e-2f, 4.166664568298827e-2f);
    const u64t CHALF  = pack2(-0.5f, -0.5f);
    const u64t CONE   = pack2(1.0f, 1.0f);
    const u64t SS3    = pack2(-1.9515295891e-4f, -1.9515295891e-4f);
    const u64t SS2    = pack2(8.3321608736e-3f, 8.3321608736e-3f);
    const u64t SS1    = pack2(-1.6666654611e-1f, -1.6666654611e-1f);

    u64t T = fma2(X, INV2, MAG2);
    float tlo, thi; unpack2(T, tlo, thi);
    int q0 = __float_as_int(tlo);
    int q1 = __float_as_int(thi);
    u64t Q = fma2(T, CONE, NMAG2);   // exact (Sterbenz), single rounding
    u64t R = fma2(Q, NPIH2, X);
    R = fma2(Q, PIL2, R);
    u64t S = mul2(R, R);             // feeds fma2 only — fusion-safe

    u64t PC = fma2(S, CC3, CC2);
    PC = fma2(S, PC, CC1);
    PC = fma2(S, PC, CHALF);
    PC = fma2(S, PC, CONE);

    u64t PS = fma2(S, SS3, SS2);
    PS = fma2(S, PS, SS1);
    u64t SR = mul2(S, R);            // feeds fma2 as multiplicand — safe
    PS = fma2(PS, SR, R);

    float pc0, pc1, ps0, ps1;
    unpack2(PC, pc0, pc1);
    unpack2(PS, ps0, ps1);

    float v0 = (q0 & 1) ? ps0 : pc0;
    float v1 = (q1 & 1) ? ps1 : pc1;
    o0 = __int_as_float(__float_as_int(v0) ^ (int)(((unsigned)(q0 + 1) & 2u) << 30));
    o1 = __int_as_float(__float_as_int(v1) ^ (int)(((unsigned)(q1 + 1) & 2u) << 30));
}

__device__ __forceinline__ float xsn(float f, unsigned w)
{
    return __int_as_float(__float_as_int(f) ^ ((int)w & 0x80000000));
}

// ---------------------------------------------------------------------------
// 128-pt FWHT, 8 consecutive elems/lane (element = (lane&15)*8 + j), 16-lane
// group per row (2 rows per warp). Stages h=1,2,4 in-register, h=8,16,32,64
// cross-lane via fmaf(±1, f, p) — identical pairing and rounding to the
// reference stage order.
// ---------------------------------------------------------------------------
__device__ __forceinline__ void fwht128_8(float f[8], float sg8, float sg16,
                                          float sg32, float sg64)
{
    // h = 1
#pragma unroll
    for (int k = 0; k < 4; k++) {
        float a = f[2*k], b = f[2*k+1];
        f[2*k] = a + b; f[2*k+1] = a - b;
    }
    // h = 2
#pragma unroll
    for (int g = 0; g < 2; g++)
#pragma unroll
        for (int j = 0; j < 2; j++) {
            int i0 = g*4 + j;
            float a = f[i0], b = f[i0+2];
            f[i0] = a + b; f[i0+2] = a - b;
        }
    // h = 4
#pragma unroll
    for (int j = 0; j < 4; j++) {
        float a = f[j], b = f[j+4];
        f[j] = a + b; f[j+4] = a - b;
    }
    // h = 8, 16, 32, 64 : cross-lane (group bits 0..3)
#pragma unroll
    for (int j = 0; j < 8; j++) {
        float p = __shfl_xor_sync(0xffffffffu, f[j], 1);
        f[j] = fmaf(sg8, f[j], p);
    }
#pragma unroll
    for (int j = 0; j < 8; j++) {
        float p = __shfl_xor_sync(0xffffffffu, f[j], 2);
        f[j] = fmaf(sg16, f[j], p);
    }
#pragma unroll
    for (int j = 0; j < 8; j++) {
        float p = __shfl_xor_sync(0xffffffffu, f[j], 4);
        f[j] = fmaf(sg32, f[j], p);
    }
#pragma unroll
    for (int j = 0; j < 8; j++) {
        float p = __shfl_xor_sync(0xffffffffu, f[j], 8);
        f[j] = fmaf(sg64, f[j], p);
    }
}

// ---------------------------------------------------------------------------
// Kernel 2: warp item = (row-pair, stack-quad). Warp holds 2 rows (lane>>4),
// 8 elems/lane; unrolled loop over 4 stacks gives cross-stack ILP (the
// property R10 lost). 65536 items / 3552 warps.
// ---------------------------------------------------------------------------
#define K2_BLOCKS  444          // 148 * 3
#define K2_THREADS 256
#define K2_NW      (K2_BLOCKS * K2_THREADS / 32)
#define NITEMS     ((NROWS / 2) * 16)       // 65536

__global__ __launch_bounds__(K2_THREADS, 3)
void fwht_cos_kernel(const float* __restrict__ xp, const float* __restrict__ d,
                     const float* __restrict__ b, float* __restrict__ out)
{
    const int lane = threadIdx.x & 31;
    const int l16  = lane & 15;
    const int g    = lane >> 4;          // row within pair
    const int gw   = (blockIdx.x * K2_THREADS + threadIdx.x) >> 5;
    const int e0   = l16 * 8;

    const float sg8  = (l16 & 1) ? -1.0f : 1.0f;
    const float sg16 = (l16 & 2) ? -1.0f : 1.0f;
    const float sg32 = (l16 & 4) ? -1.0f : 1.0f;
    const float sg64 = (l16 & 8) ? -1.0f : 1.0f;

    for (int item = gw; item < NITEMS; item += K2_NW) {
        const int rp = item >> 4;
        const int sq = item & 15;
        const int r  = rp * 2 + g;

        float xv[8];
        {
            const float4* xr = (const float4*)(xp + (size_t)r * NPCAS + e0);
#pragma unroll
            for (int i = 0; i < 2; i++) {
                float4 v = xr[i];
                xv[4*i+0] = v.x; xv[4*i+1] = v.y; xv[4*i+2] = v.z; xv[4*i+3] = v.w;
            }
        }
        float* orow = out + (size_t)r * OUTDIM;

#pragma unroll
        for (int si = 0; si < 4; si++) {
            const int s    = sq * 4 + si;
            const int base = s * NPCAS + e0;

            float f[8];
            // apply d0 signs at load (transient)
            {
                const uint4* dq = (const uint4*)(d + base);
#pragma unroll
                for (int i = 0; i < 2; i++) {
                    uint4 q = dq[i];
                    f[4*i+0] = xsn(xv[4*i+0], q.x); f[4*i+1] = xsn(xv[4*i+1], q.y);
                    f[4*i+2] = xsn(xv[4*i+2], q.z); f[4*i+3] = xsn(xv[4*i+3], q.w);
                }
            }
            fwht128_8(f, sg8, sg16, sg32, sg64);
#pragma unroll
            for (int j = 0; j < 8; j++) f[j] = __fmul_rn(f[j], COEFF_F);

            // apply d1 signs (transient)
            {
                const uint4* dq = (const uint4*)(d + NSTACKS * NPCAS + base);
#pragma unroll
                for (int i = 0; i < 2; i++) {
                    uint4 q = dq[i];
                    f[4*i+0] = xsn(f[4*i+0], q.x); f[4*i+1] = xsn(f[4*i+1], q.y);
                    f[4*i+2] = xsn(f[4*i+2], q.z); f[4*i+3] = xsn(f[4*i+3], q.w);
                }
            }
            fwht128_8(f, sg8, sg16, sg32, sg64);

            // SEPARATE scalar mul then add (two roundings) — matches reference
            {
                const float4* bq = (const float4*)(b + base);
#pragma unroll
                for (int i = 0; i < 2; i++) {
                    float4 v = bq[i];
                    f[4*i+0] = __fadd_rn(__fmul_rn(f[4*i+0], COEFF_F), __fmul_rn(v.x, TWO_PI_F));
                    f[4*i+1] = __fadd_rn(__fmul_rn(f[4*i+1], COEFF_F), __fmul_rn(v.y, TWO_PI_F));
                    f[4*i+2] = __fadd_rn(__fmul_rn(f[4*i+2], COEFF_F), __fmul_rn(v.z, TWO_PI_F));
                    f[4*i+3] = __fadd_rn(__fmul_rn(f[4*i+3], COEFF_F), __fmul_rn(v.w, TWO_PI_F));
                }
            }
            // cos in place
#pragma unroll
            for (int j = 0; j < 4; j++)
                fast_cos2(pack2(f[2*j], f[2*j+1]), f[2*j], f[2*j+1]);

            // store
#pragma unroll
            for (int i = 0; i < 2; i++)
                *(float4*)(orow + base + 4*i) =
                    make_float4(f[4*i+0], f[4*i+1], f[4*i+2], f[4*i+3]);
        }
    }
}

// ---------------------------------------------------------------------------
extern "C" void kernel_launch(void* const* d_in, const int* in_sizes, int n_in,
                              void* d_out, int out_size)
{
    const float* x    = (const float*)d_in[0];
    const float* proj = (const float*)d_in[1];
    const float* d    = (const float*)d_in[2];
    const float* b    = (const float*)d_in[3];
    float* out        = (float*)d_out;

    float* xproj;
    cudaGetSymbolAddress((void**)&xproj, g_xproj);

    gemm_kernel<<<NROWS / 64, 256>>>(x, proj, xproj);
    fwht_cos_kernel<<<K2_BLOCKS, K2_THREADS>>>(xproj, d, b, out);
}

// round 14
// speedup vs baseline: 2.2080x; 1.1304x over previous
#include <cuda_runtime.h>
#include <cstdint>

#define NROWS   8192
#define KDIM    512
#define NPCAS   128
#define NSTACKS 64
#define OUTDIM  8192

#define COEFF_F   3.7712361663282537f
#define TWO_PI_F  6.283185307179586f

__device__ float g_xproj[NROWS * NPCAS];

// ---------------------------------------------------------------------------
// Kernel 1: 32 rows/block (grid 256 = better SM coverage than 128).
// Per-element accumulation order IDENTICAL to previous (ascending k through
// the same 64-wide chunks) — bit-exact vs reference.
// ---------------------------------------------------------------------------
__global__ __launch_bounds__(256, 2)
void gemm_kernel(const float* __restrict__ A, const float* __restrict__ B,
                 float* __restrict__ C)
{
    __shared__ float As[32 * 64];    // 8KB
    __shared__ float Bs[64 * 128];   // 32KB

    const int tid  = threadIdx.x;
    const int r0   = blockIdx.x * 32;
    const int warp = tid >> 5;
    const int lane = tid & 31;
    const int rbase = warp * 4;      // 4 rows per warp
    const int cb    = lane * 4;

    float acc[4][4];
#pragma unroll
    for (int i = 0; i < 4; i++)
#pragma unroll
        for (int j = 0; j < 4; j++) acc[i][j] = 0.0f;

    for (int kc = 0; kc < KDIM; kc += 64) {
        __syncthreads();
        // load A chunk: 32 rows x 64 k = 512 float4
#pragma unroll
        for (int i = 0; i < 2; i++) {
            int idx = tid + i * 256;
            int row = idx >> 4;
            int k4  = idx & 15;
            ((float4*)As)[row * 16 + k4] =
                *(const float4*)(A + (size_t)(r0 + row) * KDIM + kc + k4 * 4);
        }
        // load B chunk: 64 k x 128 c = 2048 float4
#pragma unroll
        for (int i = 0; i < 8; i++) {
            int idx = tid + i * 256;
            int kk  = idx >> 5;
            int c4  = idx & 31;
            ((float4*)Bs)[kk * 32 + c4] =
                *(const float4*)(B + (size_t)(kc + kk) * NPCAS + c4 * 4);
        }
        __syncthreads();

#pragma unroll 8
        for (int kk = 0; kk < 64; kk++) {
            float4 b4 = ((const float4*)Bs)[kk * 32 + lane];
#pragma unroll
            for (int i = 0; i < 4; i++) {
                float a = As[(rbase + i) * 64 + kk];
                acc[i][0] = fmaf(a, b4.x, acc[i][0]);
                acc[i][1] = fmaf(a, b4.y, acc[i][1]);
                acc[i][2] = fmaf(a, b4.z, acc[i][2]);
                acc[i][3] = fmaf(a, b4.w, acc[i][3]);
            }
        }
    }

#pragma unroll
    for (int i = 0; i < 4; i++) {
        float4 v = make_float4(acc[i][0], acc[i][1], acc[i][2], acc[i][3]);
        *(float4*)(C + (size_t)(r0 + rbase + i) * NPCAS + cb) = v;
    }
}

// ---------------------------------------------------------------------------
// Packed f32x2 helpers. R7 lesson: never emit packed mul.rn feeding packed
// add.rn where two roundings are required — ptxas fuses them into fma.
// ---------------------------------------------------------------------------
typedef unsigned long long u64t;

__device__ __forceinline__ u64t pack2(float lo, float hi) {
    u64t r; asm("mov.b64 %0, {%1, %2};" : "=l"(r) : "f"(lo), "f"(hi)); return r;
}
__device__ __forceinline__ void unpack2(u64t v, float& lo, float& hi) {
    asm("mov.b64 {%0, %1}, %2;" : "=f"(lo), "=f"(hi) : "l"(v));
}
__device__ __forceinline__ u64t fma2(u64t a, u64t b, u64t c) {
    u64t r; asm("fma.rn.f32x2 %0, %1, %2, %3;" : "=l"(r) : "l"(a), "l"(b), "l"(c)); return r;
}
__device__ __forceinline__ u64t mul2(u64t a, u64t b) {
    u64t r; asm("mul.rn.f32x2 %0, %1, %2;" : "=l"(r) : "l"(a), "l"(b)); return r;
}

// Packed cos, per-half bit-identical to the scalar fast_cos (R4-verified).
__device__ __forceinline__ void fast_cos2(u64t X, float& o0, float& o1)
{
    const u64t INV2   = pack2(0.6366197723675814f, 0.6366197723675814f);
    const u64t MAG2   = pack2(12582912.0f, 12582912.0f);
    const u64t NMAG2  = pack2(-12582912.0f, -12582912.0f);
    const u64t NPIH2  = pack2(-1.5707963705062866f, -1.5707963705062866f);
    const u64t PIL2   = pack2(4.3711388286737929e-8f, 4.3711388286737929e-8f);
    const u64t CC3    = pack2(2.443315711809948e-5f, 2.443315711809948e-5f);
    const u64t CC2    = pack2(-1.388731625493765e-3f, -1.388731625493765e-3f);
    const u64t CC1    = pack2(4.166664568298827e-2f, 4.166664568298827e-2f);
    const u64t CHALF  = pack2(-0.5f, -0.5f);
    const u64t CONE   = pack2(1.0f, 1.0f);
    const u64t SS3    = pack2(-1.9515295891e-4f, -1.9515295891e-4f);
    const u64t SS2    = pack2(8.3321608736e-3f, 8.3321608736e-3f);
    const u64t SS1    = pack2(-1.6666654611e-1f, -1.6666654611e-1f);

    u64t T = fma2(X, INV2, MAG2);
    float tlo, thi; unpack2(T, tlo, thi);
    int q0 = __float_as_int(tlo);
    int q1 = __float_as_int(thi);
    u64t Q = fma2(T, CONE, NMAG2);   // exact (Sterbenz), single rounding
    u64t R = fma2(Q, NPIH2, X);
    R = fma2(Q, PIL2, R);
    u64t S = mul2(R, R);             // feeds fma2 only — fusion-safe

    u64t PC = fma2(S, CC3, CC2);
    PC = fma2(S, PC, CC1);
    PC = fma2(S, PC, CHALF);
    PC = fma2(S, PC, CONE);

    u64t PS = fma2(S, SS3, SS2);
    PS = fma2(S, PS, SS1);
    u64t SR = mul2(S, R);            // feeds fma2 as multiplicand — safe
    PS = fma2(PS, SR, R);

    float pc0, pc1, ps0, ps1;
    unpack2(PC, pc0, pc1);
    unpack2(PS, ps0, ps1);

    float v0 = (q0 & 1) ? ps0 : pc0;
    float v1 = (q1 & 1) ? ps1 : pc1;
    o0 = __int_as_float(__float_as_int(v0) ^ (int)(((unsigned)(q0 + 1) & 2u) << 30));
    o1 = __int_as_float(__float_as_int(v1) ^ (int)(((unsigned)(q1 + 1) & 2u) << 30));
}

__device__ __forceinline__ float xor_signw(float f, unsigned w)
{
    return __int_as_float(__float_as_int(f) ^ ((int)w & 0x80000000));
}

// 128-pt FWHT across warp, 4 elems/lane (R8 layout — best measured).
// Cross-lane stages use fmaf(±1,f,p) (rounds identically to ±f + p).
__device__ __forceinline__ void fwht_core(float& f0, float& f1, float& f2, float& f3,
                                          unsigned d0, unsigned d1, unsigned d2, unsigned d3,
                                          const float sg1, const float sg2, const float sg4,
                                          const float sg8, const float sg16)
{
    f0 = xor_signw(f0, d0); f1 = xor_signw(f1, d1);
    f2 = xor_signw(f2, d2); f3 = xor_signw(f3, d3);
    float t0 = f0 + f1, t1 = f0 - f1, t2 = f2 + f3, t3 = f2 - f3;
    f0 = t0 + t2; f1 = t1 + t3; f2 = t0 - t2; f3 = t1 - t3;
    {
        float p0 = __shfl_xor_sync(0xffffffffu, f0, 1);
        float p1 = __shfl_xor_sync(0xffffffffu, f1, 1);
        float p2 = __shfl_xor_sync(0xffffffffu, f2, 1);
        float p3 = __shfl_xor_sync(0xffffffffu, f3, 1);
        f0 = fmaf(sg1, f0, p0); f1 = fmaf(sg1, f1, p1);
        f2 = fmaf(sg1, f2, p2); f3 = fmaf(sg1, f3, p3);
    }
    {
        float p0 = __shfl_xor_sync(0xffffffffu, f0, 2);
        float p1 = __shfl_xor_sync(0xffffffffu, f1, 2);
        float p2 = __shfl_xor_sync(0xffffffffu, f2, 2);
        float p3 = __shfl_xor_sync(0xffffffffu, f3, 2);
        f0 = fmaf(sg2, f0, p0); f1 = fmaf(sg2, f1, p1);
        f2 = fmaf(sg2, f2, p2); f3 = fmaf(sg2, f3, p3);
    }
    {
        float p0 = __shfl_xor_sync(0xffffffffu, f0, 4);
        float p1 = __shfl_xor_sync(0xffffffffu, f1, 4);
        float p2 = __shfl_xor_sync(0xffffffffu, f2, 4);
        float p3 = __shfl_xor_sync(0xffffffffu, f3, 4);
        f0 = fmaf(sg4, f0, p0); f1 = fmaf(sg4, f1, p1);
        f2 = fmaf(sg4, f2, p2); f3 = fmaf(sg4, f3, p3);
    }
    {
        float p0 = __shfl_xor_sync(0xffffffffu, f0, 8);
        float p1 = __shfl_xor_sync(0xffffffffu, f1, 8);
        float p2 = __shfl_xor_sync(0xffffffffu, f2, 8);
        float p3 = __shfl_xor_sync(0xffffffffu, f3, 8);
        f0 = fmaf(sg8, f0, p0); f1 = fmaf(sg8, f1, p1);
        f2 = fmaf(sg8, f2, p2); f3 = fmaf(sg8, f3, p3);
    }
    {
        float p0 = __shfl_xor_sync(0xffffffffu, f0, 16);
        float p1 = __shfl_xor_sync(0xffffffffu, f1, 16);
        float p2 = __shfl_xor_sync(0xffffffffu, f2, 16);
        float p3 = __shfl_xor_sync(0xffffffffu, f3, 16);
        f0 = fmaf(sg16, f0, p0); f1 = fmaf(sg16, f1, p1);
        f2 = fmaf(sg16, f2, p2); f3 = fmaf(sg16, f3, p3);
    }
}

// ---------------------------------------------------------------------------
// Kernel 2: R8 structure (best measured), grid raised to 5 blocks/SM.
// ---------------------------------------------------------------------------
#define K2_BLOCKS  740          // 148 * 5
#define K2_THREADS 256
#define K2_NW      (K2_BLOCKS * K2_THREADS / 32)
#define NITEMS     (NROWS * 8)

__global__ __launch_bounds__(K2_THREADS)
void fwht_cos_kernel(const float* __restrict__ xp, const float* __restrict__ d,
                     const float* __restrict__ b, float* __restrict__ out)
{
    const int lane = threadIdx.x & 31;
    const int gw   = (blockIdx.x * K2_THREADS + threadIdx.x) >> 5;
    const int e    = lane * 4;

    const float sg1  = (lane & 1)  ? -1.0f : 1.0f;
    const float sg2  = (lane & 2)  ? -1.0f : 1.0f;
    const float sg4  = (lane & 4)  ? -1.0f : 1.0f;
    const float sg8  = (lane & 8)  ? -1.0f : 1.0f;
    const float sg16 = (lane & 16) ? -1.0f : 1.0f;

    for (int item = gw; item < NITEMS; item += K2_NW) {
        const int r = item >> 3;
        const int o = item & 7;

        float4 xv = *(const float4*)(xp + (size_t)r * NPCAS + e);
        float* orow = out + (size_t)r * OUTDIM;

#pragma unroll
        for (int si = 0; si < 8; si++) {
            const int s = o * 8 + si;
            uint4 dw0 = *(const uint4*)(d + (size_t)s * NPCAS + e);
            uint4 dw1 = *(const uint4*)(d + (size_t)(NSTACKS + s) * NPCAS + e);
            float4 bv = *(const float4*)(b + (size_t)s * NPCAS + e);
            float bb0 = __fmul_rn(bv.x, TWO_PI_F), bb1 = __fmul_rn(bv.y, TWO_PI_F);
            float bb2 = __fmul_rn(bv.z, TWO_PI_F), bb3 = __fmul_rn(bv.w, TWO_PI_F);

            float f0 = xv.x, f1 = xv.y, f2 = xv.z, f3 = xv.w;

            fwht_core(f0, f1, f2, f3, dw0.x, dw0.y, dw0.z, dw0.w,
                      sg1, sg2, sg4, sg8, sg16);
            f0 = __fmul_rn(f0, COEFF_F); f1 = __fmul_rn(f1, COEFF_F);
            f2 = __fmul_rn(f2, COEFF_F); f3 = __fmul_rn(f3, COEFF_F);

            fwht_core(f0, f1, f2, f3, dw1.x, dw1.y, dw1.z, dw1.w,
                      sg1, sg2, sg4, sg8, sg16);

            // SEPARATE scalar mul then add (two roundings) — matches reference
            float a0 = __fadd_rn(__fmul_rn(f0, COEFF_F), bb0);
            float a1 = __fadd_rn(__fmul_rn(f1, COEFF_F), bb1);
            float a2 = __fadd_rn(__fmul_rn(f2, COEFF_F), bb2);
            float a3 = __fadd_rn(__fmul_rn(f3, COEFF_F), bb3);

            float4 ov;
            fast_cos2(pack2(a0, a1), ov.x, ov.y);
            fast_cos2(pack2(a2, a3), ov.z, ov.w);

            *(float4*)(orow + s * NPCAS + e) = ov;
        }
    }
}

// ---------------------------------------------------------------------------
extern "C" void kernel_launch(void* const* d_in, const int* in_sizes, int n_in,
                              void* d_out, int out_size)
{
    const float* x    = (const float*)d_in[0];
    const float* proj = (const float*)d_in[1];
    const float* d    = (const float*)d_in[2];
    const float* b    = (const float*)d_in[3];
    float* out        = (float*)d_out;

    float* xproj;
    cudaGetSymbolAddress((void**)&xproj, g_xproj);

    gemm_kernel<<<NROWS / 32, 256>>>(x, proj, xproj);
    fwht_cos_kernel<<<K2_BLOCKS, K2_THREADS>>>(xproj, d, b, out);
}